// round 10
// baseline (speedup 1.0000x reference)
#include <cuda_runtime.h>

// ChamferLoss: preds [20000,3] f32, gts [1,20000,3] f32.
// Outputs (reference return order, flattened): dist1[20000], dist2[20000],
// idx1[20000], idx2[20000] — written as float32 into d_out (80000 elems).
//
// dist1/idx1: for each pred point, min squared dist (and argmin) over gts.
// dist2/idx2: for each gt point,  min squared dist (and argmin) over preds.

#define N_PTS 20000

constexpr int THREADS = 256;
constexpr int QPT     = 4;                 // queries per thread
constexpr int QBLK    = THREADS * QPT;     // 1024 queries per CTA
constexpr int NQBLK   = (N_PTS + QBLK - 1) / QBLK;   // 20
constexpr int RSPLIT  = 10;                // split reference dim for parallelism
constexpr int RCHUNK  = (N_PTS + RSPLIT - 1) / RSPLIT; // 2000
constexpr int TILE    = 512;               // refs per smem tile

// Packed (orderedDistBits << 32) | idx. Scratch — device global, no allocs.
__device__ unsigned long long g_best[2 * N_PTS];

__device__ __forceinline__ unsigned int float_to_ordered(float f) {
    unsigned int u = __float_as_uint(f);
    // monotone map float -> uint (handles negatives from fp rounding)
    return (u & 0x80000000u) ? ~u : (u | 0x80000000u);
}
__device__ __forceinline__ float ordered_to_float(unsigned int o) {
    unsigned int u = (o & 0x80000000u) ? (o ^ 0x80000000u) : ~o;
    return __uint_as_float(u);
}

__global__ void chamfer_init_kernel() {
    int i = blockIdx.x * blockDim.x + threadIdx.x;
    if (i < 2 * N_PTS) g_best[i] = 0xFFFFFFFFFFFFFFFFULL;
}

__global__ __launch_bounds__(THREADS)
void chamfer_pairs_kernel(const float* __restrict__ preds,
                          const float* __restrict__ gts) {
    const int dir = blockIdx.z;  // 0: query=preds,ref=gts (dist1); 1: query=gts,ref=preds (dist2)
    const float* __restrict__ q = (dir == 0) ? preds : gts;
    const float* __restrict__ r = (dir == 0) ? gts : preds;

    __shared__ float4 tile[TILE];

    float qx[QPT], qy[QPT], qz[QPT], qq[QPT];
    int   qi[QPT];
    float best[QPT];
    int   bidx[QPT];

#pragma unroll
    for (int k = 0; k < QPT; k++) {
        int i = blockIdx.x * QBLK + k * THREADS + threadIdx.x;
        qi[k] = i;
        float x = 0.f, y = 0.f, z = 0.f;
        if (i < N_PTS) {
            x = q[3 * i + 0];
            y = q[3 * i + 1];
            z = q[3 * i + 2];
        }
        qx[k] = x; qy[k] = y; qz[k] = z;
        qq[k] = fmaf(x, x, fmaf(y, y, z * z));
        best[k] = __int_as_float(0x7F800000);  // +inf
        bidx[k] = 0;
    }

    const int r0 = blockIdx.y * RCHUNK;
    const int r1 = min(r0 + RCHUNK, N_PTS);

    for (int base = r0; base < r1; base += TILE) {
        const int cnt = min(TILE, r1 - base);
        __syncthreads();
        for (int j = threadIdx.x; j < cnt; j += THREADS) {
            float rx = r[3 * (base + j) + 0];
            float ry = r[3 * (base + j) + 1];
            float rz = r[3 * (base + j) + 2];
            float rr = fmaf(rx, rx, fmaf(ry, ry, rz * rz));
            tile[j] = make_float4(rx, ry, rz, rr);
        }
        __syncthreads();

#pragma unroll 4
        for (int j = 0; j < cnt; j++) {
            const float4 t = tile[j];
#pragma unroll
            for (int k = 0; k < QPT; k++) {
                float dot = fmaf(qx[k], t.x, fmaf(qy[k], t.y, qz[k] * t.z));
                float d   = fmaf(-2.0f, dot, qq[k] + t.w);
                if (d < best[k]) { best[k] = d; bidx[k] = base + j; }
            }
        }
    }

#pragma unroll
    for (int k = 0; k < QPT; k++) {
        if (qi[k] < N_PTS) {
            unsigned long long packed =
                ((unsigned long long)float_to_ordered(best[k]) << 32) |
                (unsigned int)bidx[k];
            atomicMin(&g_best[dir * N_PTS + qi[k]], packed);
        }
    }
}

__global__ void chamfer_finalize_kernel(float* __restrict__ out) {
    int i = blockIdx.x * blockDim.x + threadIdx.x;
    if (i >= 2 * N_PTS) return;
    unsigned long long v = g_best[i];
    float d   = ordered_to_float((unsigned int)(v >> 32));
    float idx = (float)(unsigned int)(v & 0xFFFFFFFFu);
    if (i < N_PTS) {                    // dir 0 -> dist1 / idx1
        out[i]             = d;
        out[2 * N_PTS + i] = idx;
    } else {                            // dir 1 -> dist2 / idx2
        int j = i - N_PTS;
        out[N_PTS + j]     = d;
        out[3 * N_PTS + j] = idx;
    }
}

extern "C" void kernel_launch(void* const* d_in, const int* in_sizes, int n_in,
                              void* d_out, int out_size) {
    const float* preds = (const float*)d_in[0];  // [20000,3]
    const float* gts   = (const float*)d_in[1];  // [1,20000,3]
    float* out = (float*)d_out;

    chamfer_init_kernel<<<(2 * N_PTS + 255) / 256, 256>>>();

    dim3 grid(NQBLK, RSPLIT, 2);
    chamfer_pairs_kernel<<<grid, THREADS>>>(preds, gts);

    chamfer_finalize_kernel<<<(2 * N_PTS + 255) / 256, 256>>>(out);
}

// round 11
// speedup vs baseline: 1.0082x; 1.0082x over previous
#include <cuda_runtime.h>

// ChamferLoss: preds [20000,3] f32, gts [1,20000,3] f32.
// Outputs (reference return order, flattened): dist1[20000], dist2[20000],
// idx1[20000], idx2[20000] — written as float32 into d_out (80000 elems).
//
// dist1/idx1: for each pred point, min squared dist (and argmin) over gts.
// dist2/idx2: for each gt point,  min squared dist (and argmin) over preds.

#define N_PTS 20000

constexpr int THREADS = 256;
constexpr int QPT     = 4;                 // queries per thread
constexpr int QBLK    = THREADS * QPT;     // 1024 queries per CTA
constexpr int NQBLK   = (N_PTS + QBLK - 1) / QBLK;   // 20
constexpr int RSPLIT  = 10;                // split reference dim for parallelism
constexpr int RCHUNK  = (N_PTS + RSPLIT - 1) / RSPLIT; // 2000
constexpr int TILE    = 512;               // refs per smem tile

// Packed (orderedDistBits << 32) | idx. Scratch — device global, no allocs.
__device__ unsigned long long g_best[2 * N_PTS];

__device__ __forceinline__ unsigned int float_to_ordered(float f) {
    unsigned int u = __float_as_uint(f);
    // monotone map float -> uint (handles negatives from fp rounding)
    return (u & 0x80000000u) ? ~u : (u | 0x80000000u);
}
__device__ __forceinline__ float ordered_to_float(unsigned int o) {
    unsigned int u = (o & 0x80000000u) ? (o ^ 0x80000000u) : ~o;
    return __uint_as_float(u);
}

__global__ void chamfer_init_kernel() {
    int i = blockIdx.x * blockDim.x + threadIdx.x;
    if (i < 2 * N_PTS) g_best[i] = 0xFFFFFFFFFFFFFFFFULL;
}

__global__ __launch_bounds__(THREADS)
void chamfer_pairs_kernel(const float* __restrict__ preds,
                          const float* __restrict__ gts) {
    const int dir = blockIdx.z;  // 0: query=preds,ref=gts (dist1); 1: query=gts,ref=preds (dist2)
    const float* __restrict__ q = (dir == 0) ? preds : gts;
    const float* __restrict__ r = (dir == 0) ? gts : preds;

    __shared__ float4 tile[TILE];

    float qx[QPT], qy[QPT], qz[QPT], qq[QPT];
    int   qi[QPT];
    float best[QPT];
    int   bidx[QPT];

#pragma unroll
    for (int k = 0; k < QPT; k++) {
        int i = blockIdx.x * QBLK + k * THREADS + threadIdx.x;
        qi[k] = i;
        float x = 0.f, y = 0.f, z = 0.f;
        if (i < N_PTS) {
            x = q[3 * i + 0];
            y = q[3 * i + 1];
            z = q[3 * i + 2];
        }
        qx[k] = x; qy[k] = y; qz[k] = z;
        qq[k] = fmaf(x, x, fmaf(y, y, z * z));
        best[k] = __int_as_float(0x7F800000);  // +inf
        bidx[k] = 0;
    }

    const int r0 = blockIdx.y * RCHUNK;
    const int r1 = min(r0 + RCHUNK, N_PTS);

    for (int base = r0; base < r1; base += TILE) {
        const int cnt = min(TILE, r1 - base);
        __syncthreads();
        for (int j = threadIdx.x; j < cnt; j += THREADS) {
            float rx = r[3 * (base + j) + 0];
            float ry = r[3 * (base + j) + 1];
            float rz = r[3 * (base + j) + 2];
            float rr = fmaf(rx, rx, fmaf(ry, ry, rz * rz));
            tile[j] = make_float4(rx, ry, rz, rr);
        }
        __syncthreads();

#pragma unroll 4
        for (int j = 0; j < cnt; j++) {
            const float4 t = tile[j];
#pragma unroll
            for (int k = 0; k < QPT; k++) {
                float dot = fmaf(qx[k], t.x, fmaf(qy[k], t.y, qz[k] * t.z));
                float d   = fmaf(-2.0f, dot, qq[k] + t.w);
                if (d < best[k]) { best[k] = d; bidx[k] = base + j; }
            }
        }
    }

#pragma unroll
    for (int k = 0; k < QPT; k++) {
        if (qi[k] < N_PTS) {
            unsigned long long packed =
                ((unsigned long long)float_to_ordered(best[k]) << 32) |
                (unsigned int)bidx[k];
            atomicMin(&g_best[dir * N_PTS + qi[k]], packed);
        }
    }
}

__global__ void chamfer_finalize_kernel(float* __restrict__ out) {
    int i = blockIdx.x * blockDim.x + threadIdx.x;
    if (i >= 2 * N_PTS) return;
    unsigned long long v = g_best[i];
    float d   = ordered_to_float((unsigned int)(v >> 32));
    float idx = (float)(unsigned int)(v & 0xFFFFFFFFu);
    if (i < N_PTS) {                    // dir 0 -> dist1 / idx1
        out[i]             = d;
        out[2 * N_PTS + i] = idx;
    } else {                            // dir 1 -> dist2 / idx2
        int j = i - N_PTS;
        out[N_PTS + j]     = d;
        out[3 * N_PTS + j] = idx;
    }
}

extern "C" void kernel_launch(void* const* d_in, const int* in_sizes, int n_in,
                              void* d_out, int out_size) {
    const float* preds = (const float*)d_in[0];  // [20000,3]
    const float* gts   = (const float*)d_in[1];  // [1,20000,3]
    float* out = (float*)d_out;

    chamfer_init_kernel<<<(2 * N_PTS + 255) / 256, 256>>>();

    dim3 grid(NQBLK, RSPLIT, 2);
    chamfer_pairs_kernel<<<grid, THREADS>>>(preds, gts);

    chamfer_finalize_kernel<<<(2 * N_PTS + 255) / 256, 256>>>(out);
}